// round 9
// baseline (speedup 1.0000x reference)
#include <cuda_runtime.h>
#include <cuda_bf16.h>
#include <math.h>
#include <cstdint>

// Problem constants
#define NB     32
#define HQ     32
#define HKV    8
#define NREP   4
#define HD     128
#define DIM    4096
#define KVD    1024
#define MAXSEQ 4096
#define NEWPOS 4095

#define QKV_OUTS 6144
#define NSPLIT 16
#define SCHUNK 256

// mma GEMM config
#define TCKS   8        // k-split
#define KBLK   512      // K per block
#define NCHUNK 16       // chunks of 32 k per block

// ---------------- scratch (device globals) ------------------------------------
__device__ float g_qkvp[TCKS * NB * QKV_OUTS];
__device__ float g_q   [NB * DIM];
__device__ float g_kn  [NB * KVD];
__device__ float g_vn  [NB * KVD];
__device__ float g_pm  [NB * HKV * NSPLIT * NREP];
__device__ float g_pl  [NB * HKV * NSPLIT * NREP];
__device__ float g_pacc[NB * HKV * NSPLIT * NREP * HD];
__device__ float g_xhi [NB * DIM];
__device__ float g_xlo [NB * DIM];
__device__ float g_ahi [NB * DIM];
__device__ float g_alo [NB * DIM];
__device__ float g_op  [TCKS * NB * DIM];

// ---------------- helpers -------------------------------------------------------
__device__ __forceinline__ unsigned long long f2fma(unsigned long long a,
                                                    unsigned long long b,
                                                    unsigned long long c) {
    unsigned long long d;
    asm("fma.rn.f32x2 %0, %1, %2, %3;" : "=l"(d) : "l"(a), "l"(b), "l"(c));
    return d;
}
__device__ __forceinline__ float2 uf2(unsigned long long u) {
    float2 f;
    asm("mov.b64 {%0, %1}, %2;" : "=f"(f.x), "=f"(f.y) : "l"(u));
    return f;
}
__device__ __forceinline__ unsigned long long dupf(float p) {
    unsigned long long u;
    asm("mov.b64 %0, {%1, %1};" : "=l"(u) : "f"(p));
    return u;
}
__device__ __forceinline__ unsigned long long pack2(float a, float b) {
    unsigned long long u;
    asm("mov.b64 %0, {%1, %2};" : "=l"(u) : "f"(a), "f"(b));
    return u;
}

// m16n8k8 tf32 HMMA: D += A * B   (A 16x8 row, B 8x8 col, fp32 accum)
__device__ __forceinline__ void mma1688(float* d, const uint32_t* a, const uint32_t* b) {
    asm volatile(
        "mma.sync.aligned.m16n8k8.row.col.f32.tf32.tf32.f32 "
        "{%0,%1,%2,%3}, {%4,%5,%6,%7}, {%8,%9}, {%0,%1,%2,%3};"
        : "+f"(d[0]), "+f"(d[1]), "+f"(d[2]), "+f"(d[3])
        : "r"(a[0]), "r"(a[1]), "r"(a[2]), "r"(a[3]), "r"(b[0]), "r"(b[1]));
}

// ------------------------------------------------------------------------------
// split x into tf32-exact hi + fp32 lo
// ------------------------------------------------------------------------------
__global__ void split_tf32(const float* __restrict__ x,
                           float* __restrict__ xhi, float* __restrict__ xlo)
{
    const int i = blockIdx.x * 256 + threadIdx.x;   // < 131072
    const float v = x[i];
    const float h = __uint_as_float(__float_as_uint(v) & 0xFFFFE000u);
    xhi[i] = h;
    xlo[i] = v - h;
}

// ------------------------------------------------------------------------------
// HMMA tf32 GEMM: yp[ks][b][o] = sum_{k in split} x[b,k] * W[o,k].
// A = W (M side, 128 outs/block), B = x hi/lo (N side, 32 batch).
// grid (OUTS/128, TCKS), 256 threads. Fragment-ordered smem, double-buffered
// 32-k chunks, reg prefetch. 3-term split: Wh*xh + Wh*xl + Wl*xh.
// ------------------------------------------------------------------------------
__global__ __launch_bounds__(256)
void gemm_mma(const float* __restrict__ xhi, const float* __restrict__ xlo,
              const float* __restrict__ w0, const float* __restrict__ w1,
              const float* __restrict__ w2, int n0, int n1,
              float* __restrict__ yp, int OUTS)
{
    // fragment-ordered tiles: Wf[buf][k8][mtile][reg][lane], Xf[buf][k8][hilo][ntile][reg][lane]
    __shared__ __align__(16) float Wf[2][4][8][4][32];     // 32KB
    __shared__ __align__(16) float Xf[2][4][2][4][2][32];  // 16KB

    const int t = threadIdx.x;
    const int lane = t & 31;
    const int w = t >> 5;

    const int obase = blockIdx.x * 128;
    const float* wp;
    int orow;
    if (obase < n0)           { wp = w0; orow = obase; }
    else if (obase < n0 + n1) { wp = w1; orow = obase - n0; }
    else                      { wp = w2; orow = obase - n0 - n1; }
    const int kb = blockIdx.y * KBLK;

    // staging geometry: W 4 float4/thread (128 rows x 32 k), X 2 float4 (2 x 32 b x 32 k)
    int wr_[4], wq_[4];
#pragma unroll
    for (int i = 0; i < 4; i++) { const int e = i * 256 + t; wr_[i] = e >> 3; wq_[i] = e & 7; }
    int xh_[2], xb_[2], xq_[2];
#pragma unroll
    for (int j = 0; j < 2; j++) {
        const int e = j * 256 + t;
        xh_[j] = e >> 8; xb_[j] = (e >> 3) & 31; xq_[j] = e & 7;
    }

    const int wm = (w & 3) * 2;   // 2 M-tiles: wm, wm+1
    const int nh = w >> 2;        // 2 N-tiles: nh*2, nh*2+1

    float d[2][2][4];
#pragma unroll
    for (int mi = 0; mi < 2; mi++)
#pragma unroll
        for (int n2 = 0; n2 < 2; n2++)
#pragma unroll
            for (int r = 0; r < 4; r++) d[mi][n2][r] = 0.f;

    // prologue: prefetch chunk 0
    float4 wreg[4], xreg[2];
#pragma unroll
    for (int i = 0; i < 4; i++)
        wreg[i] = *(const float4*)&wp[(size_t)(orow + wr_[i]) * 4096 + kb + wq_[i] * 4];
#pragma unroll
    for (int j = 0; j < 2; j++) {
        const float* src = xh_[j] ? xlo : xhi;
        xreg[j] = *(const float4*)&src[(size_t)xb_[j] * 4096 + kb + xq_[j] * 4];
    }

    for (int ch = 0; ch < NCHUNK; ch++) {
        const int buf = ch & 1;
        __syncthreads();   // all readers of buf (compute ch-2) done
        // stage into fragment-ordered smem (STS.128)
#pragma unroll
        for (int i = 0; i < 4; i++) {
            const int r = wr_[i], qq = wq_[i];
            const int reg = (qq & 1) * 2 + (((r & 15) >= 8) ? 1 : 0);
            *(float4*)&Wf[buf][qq >> 1][r >> 4][reg][(r & 7) * 4] = wreg[i];
        }
#pragma unroll
        for (int j = 0; j < 2; j++) {
            *(float4*)&Xf[buf][xq_[j] >> 1][xh_[j]][xb_[j] >> 3][xq_[j] & 1][(xb_[j] & 7) * 4] = xreg[j];
        }
        __syncthreads();   // staged data visible

        // prefetch next chunk (overlaps compute)
        if (ch + 1 < NCHUNK) {
            const int kc = kb + (ch + 1) * 32;
#pragma unroll
            for (int i = 0; i < 4; i++)
                wreg[i] = *(const float4*)&wp[(size_t)(orow + wr_[i]) * 4096 + kc + wq_[i] * 4];
#pragma unroll
            for (int j = 0; j < 2; j++) {
                const float* src = xh_[j] ? xlo : xhi;
                xreg[j] = *(const float4*)&src[(size_t)xb_[j] * 4096 + kc + xq_[j] * 4];
            }
        }

#pragma unroll
        for (int k8 = 0; k8 < 4; k8++) {
            uint32_t ah[2][4], al[2][4];
#pragma unroll
            for (int mi = 0; mi < 2; mi++)
#pragma unroll
                for (int r = 0; r < 4; r++) {
                    const float av = Wf[buf][k8][wm + mi][r][lane];
                    const uint32_t hu = __float_as_uint(av) & 0xFFFFE000u;
                    ah[mi][r] = hu;
                    al[mi][r] = __float_as_uint(av - __uint_as_float(hu));
                }
            uint32_t bh[2][2], bl[2][2];
#pragma unroll
            for (int n2 = 0; n2 < 2; n2++) {
                const int nt = nh * 2 + n2;
                bh[n2][0] = __float_as_uint(Xf[buf][k8][0][nt][0][lane]);
                bh[n2][1] = __float_as_uint(Xf[buf][k8][0][nt][1][lane]);
                bl[n2][0] = __float_as_uint(Xf[buf][k8][1][nt][0][lane]);
                bl[n2][1] = __float_as_uint(Xf[buf][k8][1][nt][1][lane]);
            }
#pragma unroll
            for (int mi = 0; mi < 2; mi++)
#pragma unroll
                for (int n2 = 0; n2 < 2; n2++) {
                    mma1688(d[mi][n2], ah[mi], bh[n2]);
                    mma1688(d[mi][n2], ah[mi], bl[n2]);
                    mma1688(d[mi][n2], al[mi], bh[n2]);
                }
        }
    }

    // output: D fragment -> yp[ks][b][o]
#pragma unroll
    for (int mi = 0; mi < 2; mi++)
#pragma unroll
        for (int n2 = 0; n2 < 2; n2++)
#pragma unroll
            for (int r = 0; r < 4; r++) {
                const int o = obase + (wm + mi) * 16 + (lane >> 2) + (r >> 1) * 8;
                const int b = nh * 16 + n2 * 8 + (lane & 3) * 2 + (r & 1);
                yp[(size_t)(blockIdx.y * NB + b) * OUTS + o] = d[mi][n2][r];
            }
}

// ------------------------------------------------------------------------------
// RoPE + 8-way k-split reduce. grid 384 x 256.
// ------------------------------------------------------------------------------
__global__ void rope_reduce(const float* __restrict__ qkvp,
                            const float* __restrict__ fc,
                            const float* __restrict__ fs,
                            float* __restrict__ qout,
                            float* __restrict__ kout,
                            float* __restrict__ vout)
{
    const int idx = blockIdx.x * 256 + threadIdx.x;
    const int b  = idx / 3072;
    const int jp = idx % 3072;
    const int j0 = jp * 2;

    float v0 = 0.f, v1 = 0.f;
#pragma unroll
    for (int s = 0; s < TCKS; s++) {
        const float* p = qkvp + (size_t)(s * NB + b) * QKV_OUTS + j0;
        v0 += p[0];
        v1 += p[1];
    }
    if (j0 < DIM + KVD) {
        const int i = jp & 63;
        const float c = fc[i], s_ = fs[i];
        const float re = v0 * c - v1 * s_;
        const float im = v0 * s_ + v1 * c;
        v0 = re; v1 = im;
    }
    if (j0 < DIM) {
        qout[b * DIM + j0] = v0;
        qout[b * DIM + j0 + 1] = v1;
    } else if (j0 < DIM + KVD) {
        kout[b * KVD + (j0 - DIM)] = v0;
        kout[b * KVD + (j0 - DIM) + 1] = v1;
    } else {
        vout[b * KVD + (j0 - DIM - KVD)] = v0;
        vout[b * KVD + (j0 - DIM - KVD) + 1] = v1;
    }
}

// ------------------------------------------------------------------------------
__global__ void dummy_k() {}

// ------------------------------------------------------------------------------
// Flash-decode split attention (unchanged, 82% DRAM). grid (256, 16), 256 thr.
// ------------------------------------------------------------------------------
__global__ __launch_bounds__(256, 4)
void attn_split(const float* __restrict__ q,
                const float* __restrict__ ck,
                const float* __restrict__ cv,
                float* __restrict__ pm,
                float* __restrict__ pl,
                float* __restrict__ pacc)
{
    const int bg = blockIdx.x;
    const int b = bg >> 3, g = bg & 7;
    const int split = blockIdx.y;
    const int t = threadIdx.x;
    const int lane = t & 31, w = t >> 5;
    const int sbase = split * SCHUNK;

    __shared__ __align__(16) float sm[11012];
    float* qs   = sm;
    float* kbuf = sm + 512;
    float* sc   = sm + 8960;
    float* part = sm + 9984;
    float* mf   = sm + 11008;
    float* pvp  = kbuf;

    const float scale = 0.08838834764831845f;

    for (int i = t; i < 512; i += 256) {
        const int r = i >> 7, d = i & 127;
        qs[r * 128 + d] = q[(b * HQ + g * NREP + r) * HD + d] * scale;
    }

    const int s_loc = t & 31;
    const int dg = t >> 5;
    const int base_d = dg * 16;
    const size_t ckb = (size_t)(b * MAXSEQ) * KVD + g * HD;

    float4 kreg[4];
#pragma unroll
    for (int i = 0; i < 4; i++) {
        const int f4 = t + i * 256;
        const int row = f4 >> 5, c4 = (f4 & 31) * 4;
        kreg[i] = __ldcs((const float4*)&ck[ckb + (size_t)(sbase + row) * KVD + c4]);
    }

    float mloc = -1e30f;

    for (int tile = 0; tile < SCHUNK / 32; tile++) {
        float* kb = kbuf + (tile & 1) * 4224;
#pragma unroll
        for (int i = 0; i < 4; i++) {
            const int f4 = t + i * 256;
            const int row = f4 >> 5, c4 = (f4 & 31) * 4;
            *(float4*)&kb[row * 132 + c4] = kreg[i];
        }
        __syncthreads();

        if (tile + 1 < SCHUNK / 32) {
#pragma unroll
            for (int i = 0; i < 4; i++) {
                const int f4 = t + i * 256;
                const int row = f4 >> 5, c4 = (f4 & 31) * 4;
                kreg[i] = __ldcs((const float4*)&ck[ckb + (size_t)(sbase + (tile + 1) * 32 + row) * KVD + c4]);
            }
        }

        unsigned long long racc[4] = {0ull, 0ull, 0ull, 0ull};
#pragma unroll
        for (int c = 0; c < 4; c++) {
            ulonglong2 kk = *(const ulonglong2*)&kb[s_loc * 132 + base_d + c * 4];
#pragma unroll
            for (int r = 0; r < 4; r++) {
                ulonglong2 qq = *(const ulonglong2*)&qs[r * 128 + base_d + c * 4];
                racc[r] = f2fma(kk.x, qq.x, racc[r]);
                racc[r] = f2fma(kk.y, qq.y, racc[r]);
            }
        }
#pragma unroll
        for (int r = 0; r < 4; r++) {
            float2 f = uf2(racc[r]);
            part[(dg * 4 + r) * 32 + s_loc] = f.x + f.y;
        }
        __syncthreads();
        if (t < 128) {
            const int r = t >> 5;
            float val = 0.f;
#pragma unroll
            for (int d8 = 0; d8 < 8; d8++) val += part[(d8 * 4 + r) * 32 + lane];
            const int sg = sbase + tile * 32 + lane;
            if (sg == NEWPOS) val = -1e30f;
            sc[r * SCHUNK + tile * 32 + lane] = val;
            mloc = fmaxf(mloc, val);
        }
    }

    if (t < 128) {
#pragma unroll
        for (int off = 16; off; off >>= 1)
            mloc = fmaxf(mloc, __shfl_xor_sync(0xffffffffu, mloc, off));
        if (lane == 0) mf[t >> 5] = mloc;
    }
    __syncthreads();

    {
        const int r = t >> 6, s0 = t & 63;
        const float m = mf[r];
        float ls = 0.f;
#pragma unroll
        for (int j = 0; j < SCHUNK / 64; j++) {
            const int sl = s0 + j * 64;
            const float p = __expf(sc[r * SCHUNK + sl] - m);
            sc[r * SCHUNK + sl] = p;
            ls += p;
        }
#pragma unroll
        for (int off = 16; off; off >>= 1)
            ls += __shfl_xor_sync(0xffffffffu, ls, off);
        if (lane == 0) part[w] = ls;
    }
    __syncthreads();
    if (t < 4) {
        pm[bg * (NSPLIT * NREP) + split * NREP + t] = mf[t];
        pl[bg * (NSPLIT * NREP) + split * NREP + t] = part[2 * t] + part[2 * t + 1];
    }

    {
        const int dq = lane;
        const int sg8 = w;
        const size_t cvb = (size_t)(b * MAXSEQ) * KVD + g * HD + dq * 4;
        unsigned long long a[4][2];
#pragma unroll
        for (int r = 0; r < 4; r++) { a[r][0] = 0ull; a[r][1] = 0ull; }
        for (int i0 = 0; i0 < 32; i0 += 4) {
            float4 vf[4];
#pragma unroll
            for (int j = 0; j < 4; j++) {
                const int sl = sg8 * 32 + i0 + j;
                vf[j] = __ldcs((const float4*)&cv[cvb + (size_t)(sbase + sl) * KVD]);
            }
#pragma unroll
            for (int j = 0; j < 4; j++) {
                const int sl = sg8 * 32 + i0 + j;
                const unsigned long long vx = pack2(vf[j].x, vf[j].y);
                const unsigned long long vy = pack2(vf[j].z, vf[j].w);
#pragma unroll
                for (int r = 0; r < 4; r++) {
                    const unsigned long long pp = dupf(sc[r * SCHUNK + sl]);
                    a[r][0] = f2fma(pp, vx, a[r][0]);
                    a[r][1] = f2fma(pp, vy, a[r][1]);
                }
            }
        }
#pragma unroll
        for (int r = 0; r < 4; r++) {
            float2 f0 = uf2(a[r][0]), f1 = uf2(a[r][1]);
            float4 o4 = make_float4(f0.x, f0.y, f1.x, f1.y);
            *(float4*)&pvp[(sg8 * 4 + r) * 128 + dq * 4] = o4;
        }
    }
    __syncthreads();
#pragma unroll
    for (int i = 0; i < 2; i++) {
        const int idx = t + i * 256;
        const int r = idx >> 7, d = idx & 127;
        float v = 0.f;
#pragma unroll
        for (int sgp = 0; sgp < 8; sgp++) v += pvp[(sgp * 4 + r) * 128 + d];
        pacc[((bg * NSPLIT + split) * NREP + r) * HD + d] = v;
    }
}

// ------------------------------------------------------------------------------
// Combine partials + new token; emit attn as tf32 hi/lo for the wo GEMM.
// grid (256, 4), 128 threads.
// ------------------------------------------------------------------------------
__global__ __launch_bounds__(128)
void attn_combine(const float* __restrict__ q,
                  const float* __restrict__ kn,
                  const float* __restrict__ vn,
                  const float* __restrict__ pm,
                  const float* __restrict__ pl,
                  const float* __restrict__ pacc,
                  float* __restrict__ ahi,
                  float* __restrict__ alo)
{
    const int bg = blockIdx.x;
    const int b = bg >> 3, g = bg & 7;
    const int rr = blockIdx.y;
    const int t = threadIdx.x, lane = t & 31;
    __shared__ float sn1;
    const float scale = 0.08838834764831845f;

    if (t < 32) {
        const float4 k4 = *(const float4*)&kn[(b * HKV + g) * HD + lane * 4];
        const float4 q4 = *(const float4*)&q[(b * HQ + g * NREP + rr) * HD + lane * 4];
        float ds = k4.x * q4.x + k4.y * q4.y + k4.z * q4.z + k4.w * q4.w;
#pragma unroll
        for (int off = 16; off; off >>= 1) ds += __shfl_xor_sync(0xffffffffu, ds, off);
        if (lane == 0) sn1 = ds * scale;
    }
    __syncthreads();

    const int d = t;
    const float vnew = vn[(b * HKV + g) * HD + d];

    float mi[NSPLIT];
    float M = sn1;
#pragma unroll
    for (int i = 0; i < NSPLIT; i++) {
        mi[i] = pm[bg * (NSPLIT * NREP) + i * NREP + rr];
        M = fmaxf(M, mi[i]);
    }
    const float en = __expf(sn1 - M);
    float L = en;
    float num = en * vnew;
#pragma unroll
    for (int i = 0; i < NSPLIT; i++) {
        const float e = __expf(mi[i] - M);
        L += pl[bg * (NSPLIT * NREP) + i * NREP + rr] * e;
        num += pacc[((bg * NSPLIT + i) * NREP + rr) * HD + d] * e;
    }
    const float v = num / L;
    const float h = __uint_as_float(__float_as_uint(v) & 0xFFFFE000u);
    const int idx = (b * HQ + g * NREP + rr) * HD + d;
    ahi[idx] = h;
    alo[idx] = v - h;
}

// ------------------------------------------------------------------------------
// Final 8-way reduce of wo partials -> d_out. grid 512 x 256.
// ------------------------------------------------------------------------------
__global__ void final_reduce(const float* __restrict__ op, float* __restrict__ out)
{
    const int idx = blockIdx.x * 256 + threadIdx.x;
    float v = 0.f;
#pragma unroll
    for (int s = 0; s < TCKS; s++) v += op[(size_t)s * NB * DIM + idx];
    out[idx] = v;
}

// ------------------------------------------------------------------------------
extern "C" void kernel_launch(void* const* d_in, const int* in_sizes, int n_in,
                              void* d_out, int out_size)
{
    const float* x  = (const float*)d_in[0];
    const float* ck = (const float*)d_in[1];
    const float* cv = (const float*)d_in[2];
    const float* wq = (const float*)d_in[3];
    const float* wk = (const float*)d_in[4];
    const float* wv = (const float*)d_in[5];
    const float* wo = (const float*)d_in[6];
    const float* fc = (const float*)d_in[7];
    const float* fs = (const float*)d_in[8];
    float* out = (float*)d_out;

    float *qkvp, *qb, *kn, *vn, *pm, *pl, *pacc, *xhi, *xlo, *ahi, *alo, *op;
    cudaGetSymbolAddress((void**)&qkvp, g_qkvp);
    cudaGetSymbolAddress((void**)&qb,   g_q);
    cudaGetSymbolAddress((void**)&kn,   g_kn);
    cudaGetSymbolAddress((void**)&vn,   g_vn);
    cudaGetSymbolAddress((void**)&pm,   g_pm);
    cudaGetSymbolAddress((void**)&pl,   g_pl);
    cudaGetSymbolAddress((void**)&pacc, g_pacc);
    cudaGetSymbolAddress((void**)&xhi,  g_xhi);
    cudaGetSymbolAddress((void**)&xlo,  g_xlo);
    cudaGetSymbolAddress((void**)&ahi,  g_ahi);
    cudaGetSymbolAddress((void**)&alo,  g_alo);
    cudaGetSymbolAddress((void**)&op,   g_op);

    // 0) x -> tf32 hi/lo split
    split_tf32<<<512, 256>>>(x, xhi, xlo);
    // 1-2) dummies — put the qkv HMMA GEMM in the ncu capture slot (#3)
    dummy_k<<<1, 32>>>();
    dummy_k<<<1, 32>>>();
    // 3) QKV projection on tensor cores (HMMA tf32, 3-term split)
    gemm_mma<<<dim3(QKV_OUTS / 128, TCKS), 256>>>(
        xhi, xlo, wq, wk, wv, DIM, KVD, qkvp, QKV_OUTS);
    // 4) 8-way reduce + RoPE
    rope_reduce<<<384, 256>>>(qkvp, fc, fs, qb, kn, vn);
    // 5) split attention over cached tokens (pos 4095 masked)
    attn_split<<<dim3(NB * HKV, NSPLIT), 256>>>(qb, ck, cv, pm, pl, pacc);
    // 6) combine + new token; emit hi/lo
    attn_combine<<<dim3(NB * HKV, NREP), 128>>>(qb, kn, vn, pm, pl, pacc, ahi, alo);
    // 7) output projection on tensor cores
    gemm_mma<<<dim3(DIM / 128, TCKS), 256>>>(
        ahi, alo, wo, wo, wo, DIM, 0, op, DIM);
    // 8) reduce to d_out
    final_reduce<<<512, 256>>>(op, out);
}